// round 7
// baseline (speedup 1.0000x reference)
#include <cuda_runtime.h>
#include <cuda_fp16.h>
#include <cstdint>
#include <cstddef>

// ---------------------------------------------------------------------------
// RotatE scoring on base-target sm_103 (no tcgen05 on base target):
//   C[b,n] = sum_d( sre[b,d]*ent_re[n,d] + sim[b,d]*ent_im[n,d] )
// SINGLE-PASS fp16 GEMM (fp32 accum, mma.sync m16n8k16), rel_err ~2.9e-4.
//   M=1024, N=100000, K=2048 (re||im concat).
// R6: CTA tile 128x256, warp tile 64x64 (8 warps), 1 CTA/SM.
//     ldsm:mma ratio 8:32 (was 6:16); one sync per 2x the compute.
// ---------------------------------------------------------------------------

#define N_ENT   100000
#define DIM     1024
#define BATCH   1024
#define K2      2048

#define TILE_M  128
#define TILE_N  256
#define KC      32
#define NCH     (K2 / KC)        // 64
#define PITCH   80               // SMEM row pitch (bytes): conflict-free ldmatrix
#define ATSZ    (TILE_M * PITCH) // 10240
#define BTSZ    (TILE_N * PITCH) // 20480
#define STG     (ATSZ + BTSZ)    // 30720
#define NSTAGE  4
#define SMEM_DYN (NSTAGE * STG)  // 122880

__device__ __half g_A[(size_t)BATCH * K2];
__device__ __half g_B[(size_t)N_ENT * K2];

// ---------------------------- helpers --------------------------------------
__device__ __forceinline__ uint32_t smem_u32(const void* p) {
    uint32_t a;
    asm("{ .reg .u64 t; cvta.to.shared.u64 t, %1; cvt.u32.u64 %0, t; }"
        : "=r"(a) : "l"(p));
    return a;
}

__device__ __forceinline__ void cpasync16(uint32_t s, const void* g) {
    asm volatile("cp.async.cg.shared.global [%0], [%1], 16;"
                 :: "r"(s), "l"(__cvta_generic_to_global(g)));
}
__device__ __forceinline__ void cp_commit() {
    asm volatile("cp.async.commit_group;");
}
template <int N>
__device__ __forceinline__ void cp_wait() {
    asm volatile("cp.async.wait_group %0;" :: "n"(N));
}

__device__ __forceinline__ void ldsm4(uint32_t* r, uint32_t addr) {
    asm volatile("ldmatrix.sync.aligned.m8n8.x4.shared.b16 {%0,%1,%2,%3}, [%4];"
                 : "=r"(r[0]), "=r"(r[1]), "=r"(r[2]), "=r"(r[3]) : "r"(addr));
}

__device__ __forceinline__ void mma16816(float* c, const uint32_t* a,
                                         uint32_t b0, uint32_t b1) {
    asm volatile(
        "mma.sync.aligned.m16n8k16.row.col.f32.f16.f16.f32 "
        "{%0,%1,%2,%3}, {%4,%5,%6,%7}, {%8,%9}, {%0,%1,%2,%3};"
        : "+f"(c[0]), "+f"(c[1]), "+f"(c[2]), "+f"(c[3])
        : "r"(a[0]), "r"(a[1]), "r"(a[2]), "r"(a[3]), "r"(b0), "r"(b1));
}

__device__ __forceinline__ uint32_t pack2h(__half a, __half b) {
    return (uint32_t)__half_as_ushort(a) |
           ((uint32_t)__half_as_ushort(b) << 16);
}

// ---------------------- prep kernels ---------------------------------------
__global__ void __launch_bounds__(256)
prep_A(const int* __restrict__ e1, const int* __restrict__ r,
       const float* __restrict__ ent_re, const float* __restrict__ ent_im,
       const float* __restrict__ phase) {
    const int b = blockIdx.x;
    const int e = e1[b];
    const int rl = r[b];
    const float* hr = ent_re + (size_t)e * DIM;
    const float* hm = ent_im + (size_t)e * DIM;
    const float* ph = phase + (size_t)rl * DIM;
    for (int d = threadIdx.x; d < DIM; d += 256) {
        float a = hr[d], bb = hm[d], p = ph[d];
        float sn, cs;
        sincosf(p, &sn, &cs);
        float sre = a * cs - bb * sn;
        float sim = a * sn + bb * cs;
        size_t o = (size_t)b * K2 + d;
        g_A[o]       = __float2half_rn(sre);
        g_A[o + DIM] = __float2half_rn(sim);
    }
}

__global__ void __launch_bounds__(256)
prep_B(const float* __restrict__ ent_re, const float* __restrict__ ent_im) {
    const int n = blockIdx.x;
#pragma unroll
    for (int j = 0; j < 2; ++j) {
        int idx = threadIdx.x + j * 256;            // 0..511 float4 slots
        const float* src = (idx < 256)
            ? ent_re + (size_t)n * DIM + idx * 4
            : ent_im + (size_t)n * DIM + (idx - 256) * 4;
        float4 v = *(const float4*)src;
        uint2 hp;
        hp.x = pack2h(__float2half_rn(v.x), __float2half_rn(v.y));
        hp.y = pack2h(__float2half_rn(v.z), __float2half_rn(v.w));
        *(uint2*)(g_B + (size_t)n * K2 + (size_t)idx * 4) = hp;
    }
}

// ---------------------- GEMM kernel ----------------------------------------
__global__ void __launch_bounds__(256, 1)
gemm_kernel(float* __restrict__ out) {
    extern __shared__ char smem[];
    const uint32_t sb0 = smem_u32(smem);

    const int tid = threadIdx.x;
    const int lane = tid & 31;
    const int wid = tid >> 5;
    const int wm = wid & 1;        // 2 M-blocks of 64
    const int wn = wid >> 1;       // 4 N-blocks of 64
    const int m0 = blockIdx.x * TILE_M;
    const int n0 = blockIdx.y * TILE_N;

    // cp.async addressing: 16B per thread-slot, 4 slots per 80B row
    const int row0 = tid >> 2;     // 0..63
    const int c16 = tid & 3;

    // ldmatrix base offsets within a stage (fragment maps validated R3-R5)
    const uint32_t aRow = (uint32_t)((wm * 64 + (lane & 15)) * PITCH + (lane >> 4) * 16);
    const uint32_t bRow = (uint32_t)((wn * 64 + (lane & 15)) * PITCH + (lane >> 4) * 16);

    float acc[4][8][4];
#pragma unroll
    for (int a = 0; a < 4; ++a)
#pragma unroll
        for (int b = 0; b < 8; ++b)
#pragma unroll
            for (int c = 0; c < 4; ++c) acc[a][b][c] = 0.f;

    // ---- load one K-chunk into stage i%NSTAGE ----
    auto load_chunk = [&](int i) {
        const uint32_t sb = sb0 + (i % NSTAGE) * STG;
        const int kc = i * KC;
#pragma unroll
        for (int j = 0; j < 2; ++j) {          // A: 128 rows
            const int row = row0 + j * 64;
            const uint32_t so = (uint32_t)(row * PITCH + c16 * 16);
            const size_t ga = (size_t)(m0 + row) * K2 + kc + c16 * 8;
            cpasync16(sb + so, g_A + ga);
        }
#pragma unroll
        for (int j = 0; j < 4; ++j) {          // B: 256 rows
            const int row = row0 + j * 64;
            const uint32_t so = (uint32_t)(row * PITCH + c16 * 16);
            int n = n0 + row;
            if (n > N_ENT - 1) n = N_ENT - 1;
            const size_t gb = (size_t)n * K2 + kc + c16 * 8;
            cpasync16(sb + ATSZ + so, g_B + gb);
        }
    };

    load_chunk(0); cp_commit();
    load_chunk(1); cp_commit();
    load_chunk(2); cp_commit();

    for (int i = 0; i < NCH; ++i) {
        cp_wait<2>();              // group i complete (stage i%4 ready)
        __syncthreads();           // all warps done with stage (i+3)%4's prior use

        if (i + 3 < NCH) load_chunk(i + 3);
        cp_commit();               // commit (possibly empty) group i+3

        const uint32_t sb = sb0 + (i % NSTAGE) * STG;
#pragma unroll
        for (int kk = 0; kk < 2; ++kk) {
            const uint32_t ko = kk * 32;
            uint32_t ah[4][4], bh[4][4];
#pragma unroll
            for (int mi = 0; mi < 4; ++mi)
                ldsm4(ah[mi], sb + aRow + mi * (16 * PITCH) + ko);
#pragma unroll
            for (int p = 0; p < 4; ++p)
                ldsm4(bh[p], sb + ATSZ + bRow + p * (16 * PITCH) + ko);
#pragma unroll
            for (int mi = 0; mi < 4; ++mi)
#pragma unroll
                for (int p = 0; p < 4; ++p) {
                    mma16816(acc[mi][2 * p],     ah[mi], bh[p][0], bh[p][2]);
                    mma16816(acc[mi][2 * p + 1], ah[mi], bh[p][1], bh[p][3]);
                }
        }
    }

    // ---- epilogue ----
    const int mrow = m0 + wm * 64 + (lane >> 2);
    const int ncol = n0 + wn * 64 + (lane & 3) * 2;
#pragma unroll
    for (int mi = 0; mi < 4; ++mi) {
#pragma unroll
        for (int ni = 0; ni < 8; ++ni) {
            const int col = ncol + ni * 8;
            if (col < N_ENT) {
                const int r0 = mrow + mi * 16;
                float2 v0 = make_float2(acc[mi][ni][0], acc[mi][ni][1]);
                float2 v1 = make_float2(acc[mi][ni][2], acc[mi][ni][3]);
                *(float2*)(out + (size_t)r0 * N_ENT + col) = v0;
                *(float2*)(out + (size_t)(r0 + 8) * N_ENT + col) = v1;
            }
        }
    }
}

// ---------------------------- launch ---------------------------------------
extern "C" void kernel_launch(void* const* d_in, const int* in_sizes, int n_in,
                              void* d_out, int out_size) {
    const int*   e1     = (const int*)d_in[0];
    const int*   r      = (const int*)d_in[1];
    const float* ent_re = (const float*)d_in[2];
    const float* ent_im = (const float*)d_in[3];
    const float* phase  = (const float*)d_in[4];
    float* out = (float*)d_out;

    prep_A<<<BATCH, 256>>>(e1, r, ent_re, ent_im, phase);
    prep_B<<<N_ENT, 256>>>(ent_re, ent_im);

    cudaFuncSetAttribute(gemm_kernel,
                         cudaFuncAttributeMaxDynamicSharedMemorySize, SMEM_DYN);
    // m-tiles fastest: 8 CTAs sharing one entity tile are wave-co-resident,
    // so entity data is read ~once from DRAM and reused 8x through L2.
    dim3 grid(BATCH / TILE_M, (N_ENT + TILE_N - 1) / TILE_N);
    gemm_kernel<<<grid, 256, SMEM_DYN>>>(out);
}

// round 11
// speedup vs baseline: 1.0477x; 1.0477x over previous
#include <cuda_runtime.h>
#include <cuda_fp16.h>
#include <cstdint>
#include <cstddef>

// ---------------------------------------------------------------------------
// RotatE scoring on base-target sm_103 (no tcgen05 on base target):
//   C[b,n] = sum_d( sre[b,d]*ent_re[n,d] + sim[b,d]*ent_im[n,d] )
// SINGLE-PASS fp16 GEMM (fp32 accum, mma.sync m16n8k16), rel_err ~2.9e-4.
//   M=1024, N=100000, K=2048 (re||im concat).
// R7: CTA tile 128x128 with FOUR warps (128 thr), warp tile 64x64,
//     2 CTAs/SM. Combines R6's 8:32 ldsm:mma ratio (low SMEM traffic) with
//     R5's cross-CTA barrier/L2-latency cover. 4-stage cp.async pipeline.
// ---------------------------------------------------------------------------

#define N_ENT   100000
#define DIM     1024
#define BATCH   1024
#define K2      2048

#define TILE_M  128
#define TILE_N  128
#define KC      32
#define NCH     (K2 / KC)        // 64
#define PITCH   80               // SMEM row pitch (bytes): conflict-free ldmatrix
#define TSZ     (TILE_M * PITCH) // 10240 per tile
#define STG     (2 * TSZ)        // A, B -> 20480
#define NSTAGE  4
#define SMEM_DYN (NSTAGE * STG)  // 81920 (x2 CTAs = 160KB < 228KB)

__device__ __half g_A[(size_t)BATCH * K2];
__device__ __half g_B[(size_t)N_ENT * K2];

// ---------------------------- helpers --------------------------------------
__device__ __forceinline__ uint32_t smem_u32(const void* p) {
    uint32_t a;
    asm("{ .reg .u64 t; cvta.to.shared.u64 t, %1; cvt.u32.u64 %0, t; }"
        : "=r"(a) : "l"(p));
    return a;
}

__device__ __forceinline__ void cpasync16(uint32_t s, const void* g) {
    asm volatile("cp.async.cg.shared.global [%0], [%1], 16;"
                 :: "r"(s), "l"(__cvta_generic_to_global(g)));
}
__device__ __forceinline__ void cp_commit() {
    asm volatile("cp.async.commit_group;");
}
template <int N>
__device__ __forceinline__ void cp_wait() {
    asm volatile("cp.async.wait_group %0;" :: "n"(N));
}

__device__ __forceinline__ void ldsm4(uint32_t* r, uint32_t addr) {
    asm volatile("ldmatrix.sync.aligned.m8n8.x4.shared.b16 {%0,%1,%2,%3}, [%4];"
                 : "=r"(r[0]), "=r"(r[1]), "=r"(r[2]), "=r"(r[3]) : "r"(addr));
}

__device__ __forceinline__ void mma16816(float* c, const uint32_t* a,
                                         uint32_t b0, uint32_t b1) {
    asm volatile(
        "mma.sync.aligned.m16n8k16.row.col.f32.f16.f16.f32 "
        "{%0,%1,%2,%3}, {%4,%5,%6,%7}, {%8,%9}, {%0,%1,%2,%3};"
        : "+f"(c[0]), "+f"(c[1]), "+f"(c[2]), "+f"(c[3])
        : "r"(a[0]), "r"(a[1]), "r"(a[2]), "r"(a[3]), "r"(b0), "r"(b1));
}

__device__ __forceinline__ uint32_t pack2h(__half a, __half b) {
    return (uint32_t)__half_as_ushort(a) |
           ((uint32_t)__half_as_ushort(b) << 16);
}

// ---------------------- prep kernels ---------------------------------------
__global__ void __launch_bounds__(256)
prep_A(const int* __restrict__ e1, const int* __restrict__ r,
       const float* __restrict__ ent_re, const float* __restrict__ ent_im,
       const float* __restrict__ phase) {
    const int b = blockIdx.x;
    const int e = e1[b];
    const int rl = r[b];
    const float* hr = ent_re + (size_t)e * DIM;
    const float* hm = ent_im + (size_t)e * DIM;
    const float* ph = phase + (size_t)rl * DIM;
    for (int d = threadIdx.x; d < DIM; d += 256) {
        float a = hr[d], bb = hm[d], p = ph[d];
        float sn, cs;
        sincosf(p, &sn, &cs);
        float sre = a * cs - bb * sn;
        float sim = a * sn + bb * cs;
        size_t o = (size_t)b * K2 + d;
        g_A[o]       = __float2half_rn(sre);
        g_A[o + DIM] = __float2half_rn(sim);
    }
}

__global__ void __launch_bounds__(256)
prep_B(const float* __restrict__ ent_re, const float* __restrict__ ent_im) {
    const int n = blockIdx.x;
#pragma unroll
    for (int j = 0; j < 2; ++j) {
        int idx = threadIdx.x + j * 256;            // 0..511 float4 slots
        const float* src = (idx < 256)
            ? ent_re + (size_t)n * DIM + idx * 4
            : ent_im + (size_t)n * DIM + (idx - 256) * 4;
        float4 v = *(const float4*)src;
        uint2 hp;
        hp.x = pack2h(__float2half_rn(v.x), __float2half_rn(v.y));
        hp.y = pack2h(__float2half_rn(v.z), __float2half_rn(v.w));
        *(uint2*)(g_B + (size_t)n * K2 + (size_t)idx * 4) = hp;
    }
}

// ---------------------- GEMM kernel ----------------------------------------
// 128 threads = 4 warps; warp (wm, wn) owns a 64x64 sub-tile.
__global__ void __launch_bounds__(128, 2)
gemm_kernel(float* __restrict__ out) {
    extern __shared__ char smem[];
    const uint32_t sb0 = smem_u32(smem);

    const int tid = threadIdx.x;
    const int lane = tid & 31;
    const int wid = tid >> 5;      // 0..3
    const int wm = wid & 1;        // 2 M-blocks of 64
    const int wn = wid >> 1;       // 2 N-blocks of 64
    const int m0 = blockIdx.x * TILE_M;
    const int n0 = blockIdx.y * TILE_N;

    // cp.async addressing: 512 slots of 16B per tile, 128 threads -> 4 each
    // slot s: row = s>>2 (0..127), c16 = s&3
    // ldmatrix base offsets (fragment maps validated R3-R6)
    const uint32_t aRow = (uint32_t)((wm * 64 + (lane & 15)) * PITCH + (lane >> 4) * 16);
    const uint32_t bRow = (uint32_t)((wn * 64 + (lane & 15)) * PITCH + (lane >> 4) * 16);

    float acc[4][8][4];
#pragma unroll
    for (int a = 0; a < 4; ++a)
#pragma unroll
        for (int b = 0; b < 8; ++b)
#pragma unroll
            for (int c = 0; c < 4; ++c) acc[a][b][c] = 0.f;

    // ---- load one K-chunk into stage i%NSTAGE ----
    auto load_chunk = [&](int i) {
        const uint32_t sb = sb0 + (i % NSTAGE) * STG;
        const int kc = i * KC;
#pragma unroll
        for (int j = 0; j < 4; ++j) {
            const int s = tid + j * 128;            // 0..511
            const int row = s >> 2, c16 = s & 3;
            const uint32_t so = (uint32_t)(row * PITCH + c16 * 16);
            const size_t ga = (size_t)(m0 + row) * K2 + kc + c16 * 8;
            cpasync16(sb + so, g_A + ga);
            int n = n0 + row;
            if (n > N_ENT - 1) n = N_ENT - 1;       // clamp; extra rows unused
            const size_t gb = (size_t)n * K2 + kc + c16 * 8;
            cpasync16(sb + TSZ + so, g_B + gb);
        }
    };

    load_chunk(0); cp_commit();
    load_chunk(1); cp_commit();
    load_chunk(2); cp_commit();

    for (int i = 0; i < NCH; ++i) {
        cp_wait<2>();              // group i complete (stage i%4 ready)
        __syncthreads();           // all warps done with stage (i+3)%4's prior use

        if (i + 3 < NCH) load_chunk(i + 3);
        cp_commit();               // commit (possibly empty) group i+3

        const uint32_t sb = sb0 + (i % NSTAGE) * STG;
#pragma unroll
        for (int kk = 0; kk < 2; ++kk) {
            const uint32_t ko = kk * 32;
            uint32_t ah[4][4], bh[4][4];
#pragma unroll
            for (int mi = 0; mi < 4; ++mi)
                ldsm4(ah[mi], sb + aRow + mi * (16 * PITCH) + ko);
#pragma unroll
            for (int p = 0; p < 4; ++p)
                ldsm4(bh[p], sb + TSZ + bRow + p * (16 * PITCH) + ko);
#pragma unroll
            for (int mi = 0; mi < 4; ++mi)
#pragma unroll
                for (int p = 0; p < 4; ++p) {
                    mma16816(acc[mi][2 * p],     ah[mi], bh[p][0], bh[p][2]);
                    mma16816(acc[mi][2 * p + 1], ah[mi], bh[p][1], bh[p][3]);
                }
        }
    }

    // ---- epilogue ----
    const int mrow = m0 + wm * 64 + (lane >> 2);
    const int ncol = n0 + wn * 64 + (lane & 3) * 2;
#pragma unroll
    for (int mi = 0; mi < 4; ++mi) {
#pragma unroll
        for (int ni = 0; ni < 8; ++ni) {
            const int col = ncol + ni * 8;
            if (col < N_ENT) {
                const int r0 = mrow + mi * 16;
                float2 v0 = make_float2(acc[mi][ni][0], acc[mi][ni][1]);
                float2 v1 = make_float2(acc[mi][ni][2], acc[mi][ni][3]);
                *(float2*)(out + (size_t)r0 * N_ENT + col) = v0;
                *(float2*)(out + (size_t)(r0 + 8) * N_ENT + col) = v1;
            }
        }
    }
}

// ---------------------------- launch ---------------------------------------
extern "C" void kernel_launch(void* const* d_in, const int* in_sizes, int n_in,
                              void* d_out, int out_size) {
    const int*   e1     = (const int*)d_in[0];
    const int*   r      = (const int*)d_in[1];
    const float* ent_re = (const float*)d_in[2];
    const float* ent_im = (const float*)d_in[3];
    const float* phase  = (const float*)d_in[4];
    float* out = (float*)d_out;

    prep_A<<<BATCH, 256>>>(e1, r, ent_re, ent_im, phase);
    prep_B<<<N_ENT, 256>>>(ent_re, ent_im);

    cudaFuncSetAttribute(gemm_kernel,
                         cudaFuncAttributeMaxDynamicSharedMemorySize, SMEM_DYN);
    // m-tiles fastest: 8 CTAs sharing one entity tile are wave-co-resident,
    // so entity data is read ~once from DRAM and reused 8x through L2.
    dim3 grid(BATCH / TILE_M, (N_ENT + TILE_N - 1) / TILE_N);
    gemm_kernel<<<grid, 128, SMEM_DYN>>>(out);
}

// round 12
// speedup vs baseline: 1.1313x; 1.0798x over previous
#include <cuda_runtime.h>
#include <cuda_fp16.h>
#include <cstdint>
#include <cstddef>

// ---------------------------------------------------------------------------
// RotatE scoring on base-target sm_103 (no tcgen05 on base target):
//   C[b,n] = sum_d( sre[b,d]*ent_re[n,d] + sim[b,d]*ent_im[n,d] )
// SINGLE-PASS fp16 GEMM (fp32 accum, mma.sync m16n8k16), rel_err ~2.9e-4.
//   M=1024, N=100000, K=2048 (re||im concat).
// R11: R5 config (128x128 CTA, 8 warps, 64x32 warp tile, 2 CTAs/SM) with
//      KC=64 K-chunks -> 32 sync rounds instead of 64. Pitch 144 (odd*16,
//      ldmatrix conflict-free), 3-stage cp.async pipeline (221KB/SM).
// ---------------------------------------------------------------------------

#define N_ENT   100000
#define DIM     1024
#define BATCH   1024
#define K2      2048

#define TILE_M  128
#define TILE_N  128
#define KC      64
#define NCH     (K2 / KC)        // 32
#define PITCH   144              // 128B data + 16B pad: conflict-free ldmatrix
#define TSZ     (TILE_M * PITCH) // 18432 per tile
#define STG     (2 * TSZ)        // A, B -> 36864
#define NSTAGE  3
#define SMEM_DYN (NSTAGE * STG)  // 110592 (x2 CTAs = 221184 < 228KB)

__device__ __half g_A[(size_t)BATCH * K2];
__device__ __half g_B[(size_t)N_ENT * K2];

// ---------------------------- helpers --------------------------------------
__device__ __forceinline__ uint32_t smem_u32(const void* p) {
    uint32_t a;
    asm("{ .reg .u64 t; cvta.to.shared.u64 t, %1; cvt.u32.u64 %0, t; }"
        : "=r"(a) : "l"(p));
    return a;
}

__device__ __forceinline__ void cpasync16(uint32_t s, const void* g) {
    asm volatile("cp.async.cg.shared.global [%0], [%1], 16;"
                 :: "r"(s), "l"(__cvta_generic_to_global(g)));
}
__device__ __forceinline__ void cp_commit() {
    asm volatile("cp.async.commit_group;");
}
template <int N>
__device__ __forceinline__ void cp_wait() {
    asm volatile("cp.async.wait_group %0;" :: "n"(N));
}

__device__ __forceinline__ void ldsm4(uint32_t* r, uint32_t addr) {
    asm volatile("ldmatrix.sync.aligned.m8n8.x4.shared.b16 {%0,%1,%2,%3}, [%4];"
                 : "=r"(r[0]), "=r"(r[1]), "=r"(r[2]), "=r"(r[3]) : "r"(addr));
}

__device__ __forceinline__ void mma16816(float* c, const uint32_t* a,
                                         uint32_t b0, uint32_t b1) {
    asm volatile(
        "mma.sync.aligned.m16n8k16.row.col.f32.f16.f16.f32 "
        "{%0,%1,%2,%3}, {%4,%5,%6,%7}, {%8,%9}, {%0,%1,%2,%3};"
        : "+f"(c[0]), "+f"(c[1]), "+f"(c[2]), "+f"(c[3])
        : "r"(a[0]), "r"(a[1]), "r"(a[2]), "r"(a[3]), "r"(b0), "r"(b1));
}

__device__ __forceinline__ uint32_t pack2h(__half a, __half b) {
    return (uint32_t)__half_as_ushort(a) |
           ((uint32_t)__half_as_ushort(b) << 16);
}

// ---------------------- prep kernels ---------------------------------------
__global__ void __launch_bounds__(256)
prep_A(const int* __restrict__ e1, const int* __restrict__ r,
       const float* __restrict__ ent_re, const float* __restrict__ ent_im,
       const float* __restrict__ phase) {
    const int b = blockIdx.x;
    const int e = e1[b];
    const int rl = r[b];
    const float* hr = ent_re + (size_t)e * DIM;
    const float* hm = ent_im + (size_t)e * DIM;
    const float* ph = phase + (size_t)rl * DIM;
    for (int d = threadIdx.x; d < DIM; d += 256) {
        float a = hr[d], bb = hm[d], p = ph[d];
        float sn, cs;
        sincosf(p, &sn, &cs);
        float sre = a * cs - bb * sn;
        float sim = a * sn + bb * cs;
        size_t o = (size_t)b * K2 + d;
        g_A[o]       = __float2half_rn(sre);
        g_A[o + DIM] = __float2half_rn(sim);
    }
}

__global__ void __launch_bounds__(256)
prep_B(const float* __restrict__ ent_re, const float* __restrict__ ent_im) {
    const int n = blockIdx.x;
#pragma unroll
    for (int j = 0; j < 2; ++j) {
        int idx = threadIdx.x + j * 256;            // 0..511 float4 slots
        const float* src = (idx < 256)
            ? ent_re + (size_t)n * DIM + idx * 4
            : ent_im + (size_t)n * DIM + (idx - 256) * 4;
        float4 v = *(const float4*)src;
        uint2 hp;
        hp.x = pack2h(__float2half_rn(v.x), __float2half_rn(v.y));
        hp.y = pack2h(__float2half_rn(v.z), __float2half_rn(v.w));
        *(uint2*)(g_B + (size_t)n * K2 + (size_t)idx * 4) = hp;
    }
}

// ---------------------- GEMM kernel ----------------------------------------
// 256 threads = 8 warps; warp (wm, wn) owns a 64x32 sub-tile (R5-validated).
__global__ void __launch_bounds__(256, 2)
gemm_kernel(float* __restrict__ out) {
    extern __shared__ char smem[];
    const uint32_t sb0 = smem_u32(smem);

    const int tid = threadIdx.x;
    const int lane = tid & 31;
    const int wid = tid >> 5;
    const int wm = wid & 1;        // 2 M-blocks of 64
    const int wn = wid >> 1;       // 4 N-blocks of 32
    const int m0 = blockIdx.x * TILE_M;
    const int n0 = blockIdx.y * TILE_N;

    // cp.async addressing: 1024 slots of 16B per tile (128 rows x 8), 4/thread
    // ldmatrix base offsets (fragment maps validated R3-R7; pitch 144)
    const uint32_t aRow = (uint32_t)((wm * 64 + (lane & 15)) * PITCH + (lane >> 4) * 16);
    const uint32_t bRow = (uint32_t)((wn * 32 + (lane & 15)) * PITCH + (lane >> 4) * 16);

    float acc[4][4][4];
#pragma unroll
    for (int a = 0; a < 4; ++a)
#pragma unroll
        for (int b = 0; b < 4; ++b)
#pragma unroll
            for (int c = 0; c < 4; ++c) acc[a][b][c] = 0.f;

    // ---- load one K-chunk (64 halves wide) into stage i%NSTAGE ----
    auto load_chunk = [&](int i) {
        const uint32_t sb = sb0 + (i % NSTAGE) * STG;
        const int kc = i * KC;
#pragma unroll
        for (int j = 0; j < 4; ++j) {
            const int s = tid + j * 256;            // 0..1023
            const int row = s >> 3, c16 = s & 7;
            const uint32_t so = (uint32_t)(row * PITCH + c16 * 16);
            const size_t ga = (size_t)(m0 + row) * K2 + kc + c16 * 8;
            cpasync16(sb + so, g_A + ga);
            int n = n0 + row;
            if (n > N_ENT - 1) n = N_ENT - 1;       // clamp; extra rows unused
            const size_t gb = (size_t)n * K2 + kc + c16 * 8;
            cpasync16(sb + TSZ + so, g_B + gb);
        }
    };

    load_chunk(0); cp_commit();
    load_chunk(1); cp_commit();

    for (int i = 0; i < NCH; ++i) {
        cp_wait<1>();              // group i complete (stage i%3 ready)
        __syncthreads();           // all warps done with stage (i+2)%3's prior use

        if (i + 2 < NCH) load_chunk(i + 2);
        cp_commit();               // commit (possibly empty) group i+2

        const uint32_t sb = sb0 + (i % NSTAGE) * STG;
#pragma unroll
        for (int kk = 0; kk < 4; ++kk) {
            const uint32_t ko = kk * 32;
            uint32_t ah[4][4], bh[2][4];
#pragma unroll
            for (int mi = 0; mi < 4; ++mi)
                ldsm4(ah[mi], sb + aRow + mi * (16 * PITCH) + ko);
#pragma unroll
            for (int p = 0; p < 2; ++p)
                ldsm4(bh[p], sb + TSZ + bRow + p * (16 * PITCH) + ko);
#pragma unroll
            for (int mi = 0; mi < 4; ++mi)
#pragma unroll
                for (int p = 0; p < 2; ++p) {
                    mma16816(acc[mi][2 * p],     ah[mi], bh[p][0], bh[p][2]);
                    mma16816(acc[mi][2 * p + 1], ah[mi], bh[p][1], bh[p][3]);
                }
        }
    }

    // ---- epilogue (R5-validated mapping) ----
    const int mrow = m0 + wm * 64 + (lane >> 2);
    const int ncol = n0 + wn * 32 + (lane & 3) * 2;
#pragma unroll
    for (int mi = 0; mi < 4; ++mi) {
#pragma unroll
        for (int ni = 0; ni < 4; ++ni) {
            const int col = ncol + ni * 8;
            if (col < N_ENT) {
                const int r0 = mrow + mi * 16;
                float2 v0 = make_float2(acc[mi][ni][0], acc[mi][ni][1]);
                float2 v1 = make_float2(acc[mi][ni][2], acc[mi][ni][3]);
                *(float2*)(out + (size_t)r0 * N_ENT + col) = v0;
                *(float2*)(out + (size_t)(r0 + 8) * N_ENT + col) = v1;
            }
        }
    }
}

// ---------------------------- launch ---------------------------------------
extern "C" void kernel_launch(void* const* d_in, const int* in_sizes, int n_in,
                              void* d_out, int out_size) {
    const int*   e1     = (const int*)d_in[0];
    const int*   r      = (const int*)d_in[1];
    const float* ent_re = (const float*)d_in[2];
    const float* ent_im = (const float*)d_in[3];
    const float* phase  = (const float*)d_in[4];
    float* out = (float*)d_out;

    prep_A<<<BATCH, 256>>>(e1, r, ent_re, ent_im, phase);
    prep_B<<<N_ENT, 256>>>(ent_re, ent_im);

    cudaFuncSetAttribute(gemm_kernel,
                         cudaFuncAttributeMaxDynamicSharedMemorySize, SMEM_DYN);
    // m-tiles fastest: 8 CTAs sharing one entity tile are wave-co-resident,
    // so entity data is read ~once from DRAM and reused 8x through L2.
    dim3 grid(BATCH / TILE_M, (N_ENT + TILE_N - 1) / TILE_N);
    gemm_kernel<<<grid, 256, SMEM_DYN>>>(out);
}

// round 15
// speedup vs baseline: 1.1602x; 1.0255x over previous
#include <cuda_runtime.h>
#include <cuda_fp16.h>
#include <cstdint>
#include <cstddef>

// ---------------------------------------------------------------------------
// RotatE scoring on base-target sm_103 (no tcgen05 on base target):
//   C[b,n] = sum_d( sre[b,d]*ent_re[n,d] + sim[b,d]*ent_im[n,d] )
// SINGLE-PASS fp16 GEMM (fp32 accum, mma.sync m16n8k16), rel_err ~2.9e-4.
//   M=1024, N=100000, K=2048 (re||im concat).
// R13fix: identical schedule to R13 (prep_B sliced 8x on a side stream,
//   gemm slices on 2 streams gated per-slice by events -> prep/GEMM overlap;
//   measured 1428us) PLUS stream/event destruction at the end of
//   kernel_launch so no resources outlive the call (fixes the 2MB
//   teardown-baseline violation).
// ---------------------------------------------------------------------------

#define N_ENT   100000
#define DIM     1024
#define BATCH   1024
#define K2      2048

#define TILE_M  128
#define TILE_N  128
#define KC      64
#define NCH     (K2 / KC)        // 32
#define PITCH   144              // 128B data + 16B pad: conflict-free ldmatrix
#define TSZ     (TILE_M * PITCH) // 18432 per tile
#define STG     (2 * TSZ)        // A, B -> 36864
#define NSTAGE  3
#define SMEM_DYN (NSTAGE * STG)  // 110592 (x2 CTAs = 221184 < 228KB)

#define NTILES   782             // ceil(100000/128)
#define SLICES   8
#define TPS      98              // tiles per slice (last slice: 782-7*98 = 96)
#define ROWS_PS  (TPS * TILE_N)  // 12544 entity rows per slice
#define N_PAD    (NTILES * TILE_N)   // 100096 padded rows

__device__ __half g_A[(size_t)BATCH * K2];
__device__ __half g_B[(size_t)N_PAD * K2];   // padded; tail rows uninit (dead lanes)

// ---------------------------- helpers --------------------------------------
__device__ __forceinline__ uint32_t smem_u32(const void* p) {
    uint32_t a;
    asm("{ .reg .u64 t; cvta.to.shared.u64 t, %1; cvt.u32.u64 %0, t; }"
        : "=r"(a) : "l"(p));
    return a;
}

__device__ __forceinline__ void cpasync16(uint32_t s, const void* g) {
    asm volatile("cp.async.cg.shared.global [%0], [%1], 16;"
                 :: "r"(s), "l"(__cvta_generic_to_global(g)));
}
__device__ __forceinline__ void cp_commit() {
    asm volatile("cp.async.commit_group;");
}
template <int N>
__device__ __forceinline__ void cp_wait() {
    asm volatile("cp.async.wait_group %0;" :: "n"(N));
}

__device__ __forceinline__ void ldsm4(uint32_t* r, uint32_t addr) {
    asm volatile("ldmatrix.sync.aligned.m8n8.x4.shared.b16 {%0,%1,%2,%3}, [%4];"
                 : "=r"(r[0]), "=r"(r[1]), "=r"(r[2]), "=r"(r[3]) : "r"(addr));
}

__device__ __forceinline__ void mma16816(float* c, const uint32_t* a,
                                         uint32_t b0, uint32_t b1) {
    asm volatile(
        "mma.sync.aligned.m16n8k16.row.col.f32.f16.f16.f32 "
        "{%0,%1,%2,%3}, {%4,%5,%6,%7}, {%8,%9}, {%0,%1,%2,%3};"
        : "+f"(c[0]), "+f"(c[1]), "+f"(c[2]), "+f"(c[3])
        : "r"(a[0]), "r"(a[1]), "r"(a[2]), "r"(a[3]), "r"(b0), "r"(b1));
}

__device__ __forceinline__ uint32_t pack2h(__half a, __half b) {
    return (uint32_t)__half_as_ushort(a) |
           ((uint32_t)__half_as_ushort(b) << 16);
}

// ---------------------- prep kernels ---------------------------------------
__global__ void __launch_bounds__(256)
prep_A(const int* __restrict__ e1, const int* __restrict__ r,
       const float* __restrict__ ent_re, const float* __restrict__ ent_im,
       const float* __restrict__ phase) {
    const int b = blockIdx.x;
    const int e = e1[b];
    const int rl = r[b];
    const float* hr = ent_re + (size_t)e * DIM;
    const float* hm = ent_im + (size_t)e * DIM;
    const float* ph = phase + (size_t)rl * DIM;
    for (int d = threadIdx.x; d < DIM; d += 256) {
        float a = hr[d], bb = hm[d], p = ph[d];
        float sn, cs;
        sincosf(p, &sn, &cs);
        float sre = a * cs - bb * sn;
        float sim = a * sn + bb * cs;
        size_t o = (size_t)b * K2 + d;
        g_A[o]       = __float2half_rn(sre);
        g_A[o + DIM] = __float2half_rn(sim);
    }
}

// one block per entity row; 256 threads, each converts 8 floats -> one 16B store
__global__ void __launch_bounds__(256)
prep_B(const float* __restrict__ ent_re, const float* __restrict__ ent_im,
       int row0) {
    const int n = blockIdx.x + row0;
    const int t = threadIdx.x;
    const float* src = (t < 128)
        ? ent_re + (size_t)n * DIM + t * 8
        : ent_im + (size_t)n * DIM + (t - 128) * 8;
    float4 v0 = *(const float4*)src;
    float4 v1 = *(const float4*)(src + 4);
    uint4 o;
    o.x = pack2h(__float2half_rn(v0.x), __float2half_rn(v0.y));
    o.y = pack2h(__float2half_rn(v0.z), __float2half_rn(v0.w));
    o.z = pack2h(__float2half_rn(v1.x), __float2half_rn(v1.y));
    o.w = pack2h(__float2half_rn(v1.z), __float2half_rn(v1.w));
    const size_t doff = (size_t)n * K2 + ((t < 128) ? t * 8 : DIM + (t - 128) * 8);
    *(uint4*)(g_B + doff) = o;
}

// ---------------------- GEMM kernel ----------------------------------------
// 256 threads = 8 warps; warp (wm, wn) owns a 64x32 sub-tile (R5/R11 validated).
__global__ void __launch_bounds__(256, 2)
gemm_kernel(float* __restrict__ out, int tile0) {
    extern __shared__ char smem[];
    const uint32_t sb0 = smem_u32(smem);

    const int tid = threadIdx.x;
    const int lane = tid & 31;
    const int wid = tid >> 5;
    const int wm = wid & 1;        // 2 M-blocks of 64
    const int wn = wid >> 1;       // 4 N-blocks of 32
    const int m0 = blockIdx.x * TILE_M;
    const int n0 = (tile0 + blockIdx.y) * TILE_N;

    const uint32_t aRow = (uint32_t)((wm * 64 + (lane & 15)) * PITCH + (lane >> 4) * 16);
    const uint32_t bRow = (uint32_t)((wn * 32 + (lane & 15)) * PITCH + (lane >> 4) * 16);

    float acc[4][4][4];
#pragma unroll
    for (int a = 0; a < 4; ++a)
#pragma unroll
        for (int b = 0; b < 4; ++b)
#pragma unroll
            for (int c = 0; c < 4; ++c) acc[a][b][c] = 0.f;

    // ---- load one K-chunk (64 halves wide) into stage i%NSTAGE ----
    auto load_chunk = [&](int i) {
        const uint32_t sb = sb0 + (i % NSTAGE) * STG;
        const int kc = i * KC;
#pragma unroll
        for (int j = 0; j < 4; ++j) {
            const int s = tid + j * 256;            // 0..1023
            const int row = s >> 3, c16 = s & 7;
            const uint32_t so = (uint32_t)(row * PITCH + c16 * 16);
            const size_t ga = (size_t)(m0 + row) * K2 + kc + c16 * 8;
            cpasync16(sb + so, g_A + ga);
            const size_t gb = (size_t)(n0 + row) * K2 + kc + c16 * 8; // padded, no clamp
            cpasync16(sb + TSZ + so, g_B + gb);
        }
    };

    load_chunk(0); cp_commit();
    load_chunk(1); cp_commit();

    for (int i = 0; i < NCH; ++i) {
        cp_wait<1>();              // group i complete (stage i%3 ready)
        __syncthreads();           // all warps done with stage (i+2)%3's prior use

        if (i + 2 < NCH) load_chunk(i + 2);
        cp_commit();               // commit (possibly empty) group i+2

        const uint32_t sb = sb0 + (i % NSTAGE) * STG;
#pragma unroll
        for (int kk = 0; kk < 4; ++kk) {
            const uint32_t ko = kk * 32;
            uint32_t ah[4][4], bh[2][4];
#pragma unroll
            for (int mi = 0; mi < 4; ++mi)
                ldsm4(ah[mi], sb + aRow + mi * (16 * PITCH) + ko);
#pragma unroll
            for (int p = 0; p < 2; ++p)
                ldsm4(bh[p], sb + TSZ + bRow + p * (16 * PITCH) + ko);
#pragma unroll
            for (int mi = 0; mi < 4; ++mi)
#pragma unroll
                for (int p = 0; p < 2; ++p) {
                    mma16816(acc[mi][2 * p],     ah[mi], bh[p][0], bh[p][2]);
                    mma16816(acc[mi][2 * p + 1], ah[mi], bh[p][1], bh[p][3]);
                }
        }
    }

    // ---- epilogue (validated mapping) ----
    const int mrow = m0 + wm * 64 + (lane >> 2);
    const int ncol = n0 + wn * 32 + (lane & 3) * 2;
#pragma unroll
    for (int mi = 0; mi < 4; ++mi) {
#pragma unroll
        for (int ni = 0; ni < 4; ++ni) {
            const int col = ncol + ni * 8;
            if (col < N_ENT) {
                const int r0 = mrow + mi * 16;
                float2 v0 = make_float2(acc[mi][ni][0], acc[mi][ni][1]);
                float2 v1 = make_float2(acc[mi][ni][2], acc[mi][ni][3]);
                *(float2*)(out + (size_t)r0 * N_ENT + col) = v0;
                *(float2*)(out + (size_t)(r0 + 8) * N_ENT + col) = v1;
            }
        }
    }
}

// ---------------------------- launch ---------------------------------------
// Graph-parallel schedule:
//   legacy:  prep_A ──ev──┐                 gemm_0   gemm_2 ... (even slices)
//   s2:                   └─ prep_B_0..7 (events per slice)
//   s3:                                     gemm_1   gemm_3 ... (odd slices)
// Each gemm slice waits only on its own prep_B slice; two gemm streams let
// slice drains overlap. All branches join back to the legacy stream, then
// every stream/event created here is destroyed (no resources outlive the
// call -> teardown memory baseline is restored).
extern "C" void kernel_launch(void* const* d_in, const int* in_sizes, int n_in,
                              void* d_out, int out_size) {
    const int*   e1     = (const int*)d_in[0];
    const int*   r      = (const int*)d_in[1];
    const float* ent_re = (const float*)d_in[2];
    const float* ent_im = (const float*)d_in[3];
    const float* phase  = (const float*)d_in[4];
    float* out = (float*)d_out;

    cudaFuncSetAttribute(gemm_kernel,
                         cudaFuncAttributeMaxDynamicSharedMemorySize, SMEM_DYN);

    cudaStream_t s2, s3;
    cudaStreamCreateWithFlags(&s2, cudaStreamNonBlocking);
    cudaStreamCreateWithFlags(&s3, cudaStreamNonBlocking);
    cudaEvent_t evFork, evB[SLICES], evJ;
    cudaEventCreateWithFlags(&evFork, cudaEventDisableTiming);
    for (int s = 0; s < SLICES; ++s)
        cudaEventCreateWithFlags(&evB[s], cudaEventDisableTiming);
    cudaEventCreateWithFlags(&evJ, cudaEventDisableTiming);

    prep_A<<<BATCH, 256>>>(e1, r, ent_re, ent_im, phase);   // legacy stream
    cudaEventRecord(evFork, 0);
    cudaStreamWaitEvent(s2, evFork, 0);

    int row0 = 0;
    for (int s = 0; s < SLICES; ++s) {
        int rows = N_ENT - row0 < ROWS_PS ? N_ENT - row0 : ROWS_PS;
        prep_B<<<rows, 256, 0, s2>>>(ent_re, ent_im, row0);
        cudaEventRecord(evB[s], s2);
        row0 += rows;
    }

    int tile0 = 0;
    for (int s = 0; s < SLICES; ++s) {
        const int ntiles = (s < SLICES - 1) ? TPS : (NTILES - TPS * (SLICES - 1));
        cudaStream_t st = (s & 1) ? s3 : 0;
        cudaStreamWaitEvent(st, evB[s], 0);
        dim3 grid(BATCH / TILE_M, ntiles);
        gemm_kernel<<<grid, 256, SMEM_DYN, st>>>(out, tile0);
        tile0 += ntiles;
    }

    // join s3 (and transitively s2) back into the legacy stream
    cudaEventRecord(evJ, s3);
    cudaStreamWaitEvent(0, evJ, 0);

    // ---- teardown: nothing created here may outlive this call ----
    cudaStreamDestroy(s2);
    cudaStreamDestroy(s3);
    cudaEventDestroy(evFork);
    for (int s = 0; s < SLICES; ++s) cudaEventDestroy(evB[s]);
    cudaEventDestroy(evJ);
}

// round 17
// speedup vs baseline: 1.1874x; 1.0234x over previous
#include <cuda_runtime.h>
#include <cuda_fp16.h>
#include <cstdint>
#include <cstddef>

// ---------------------------------------------------------------------------
// RotatE scoring on base-target sm_103 (no tcgen05 on base target):
//   C[b,n] = sum_d( sre[b,d]*ent_re[n,d] + sim[b,d]*ent_im[n,d] )
// SINGLE-PASS fp16 GEMM (fp32 accum, mma.sync m16n8k16), rel_err ~2.9e-4.
//   M=1024, N=100000, K=2048 (re||im concat).
// R15: GEMM identical to R11/R13 winner (128x128 CTA, 8 warps, 64x32 warp
//   tile, 2 CTAs/SM, KC=64, 3-stage cp.async). Scheduling polish:
//   - prep_B fork happens BEFORE prep_A (they are independent; prep_A runs
//     concurrently with prep_B slice 0, odd gemm slices gated on evA).
//   - 16 slices (49 tiles each): first gemm starts after ~11us, finer tail
//     interleave across the two gemm streams.
//   - all streams/events destroyed before return (teardown baseline clean).
// ---------------------------------------------------------------------------

#define N_ENT   100000
#define DIM     1024
#define BATCH   1024
#define K2      2048

#define TILE_M  128
#define TILE_N  128
#define KC      64
#define NCH     (K2 / KC)        // 32
#define PITCH   144              // 128B data + 16B pad: conflict-free ldmatrix
#define TSZ     (TILE_M * PITCH) // 18432 per tile
#define STG     (2 * TSZ)        // A, B -> 36864
#define NSTAGE  3
#define SMEM_DYN (NSTAGE * STG)  // 110592 (x2 CTAs = 221184 < 228KB)

#define NTILES   782             // ceil(100000/128)
#define SLICES   16
#define TPS      49              // tiles per slice (last slice: 782-15*49 = 47)
#define ROWS_PS  (TPS * TILE_N)  // 6272 entity rows per slice
#define N_PAD    (NTILES * TILE_N)   // 100096 padded rows

__device__ __half g_A[(size_t)BATCH * K2];
__device__ __half g_B[(size_t)N_PAD * K2];   // padded; tail rows uninit (dead lanes)

// ---------------------------- helpers --------------------------------------
__device__ __forceinline__ uint32_t smem_u32(const void* p) {
    uint32_t a;
    asm("{ .reg .u64 t; cvta.to.shared.u64 t, %1; cvt.u32.u64 %0, t; }"
        : "=r"(a) : "l"(p));
    return a;
}

__device__ __forceinline__ void cpasync16(uint32_t s, const void* g) {
    asm volatile("cp.async.cg.shared.global [%0], [%1], 16;"
                 :: "r"(s), "l"(__cvta_generic_to_global(g)));
}
__device__ __forceinline__ void cp_commit() {
    asm volatile("cp.async.commit_group;");
}
template <int N>
__device__ __forceinline__ void cp_wait() {
    asm volatile("cp.async.wait_group %0;" :: "n"(N));
}

__device__ __forceinline__ void ldsm4(uint32_t* r, uint32_t addr) {
    asm volatile("ldmatrix.sync.aligned.m8n8.x4.shared.b16 {%0,%1,%2,%3}, [%4];"
                 : "=r"(r[0]), "=r"(r[1]), "=r"(r[2]), "=r"(r[3]) : "r"(addr));
}

__device__ __forceinline__ void mma16816(float* c, const uint32_t* a,
                                         uint32_t b0, uint32_t b1) {
    asm volatile(
        "mma.sync.aligned.m16n8k16.row.col.f32.f16.f16.f32 "
        "{%0,%1,%2,%3}, {%4,%5,%6,%7}, {%8,%9}, {%0,%1,%2,%3};"
        : "+f"(c[0]), "+f"(c[1]), "+f"(c[2]), "+f"(c[3])
        : "r"(a[0]), "r"(a[1]), "r"(a[2]), "r"(a[3]), "r"(b0), "r"(b1));
}

__device__ __forceinline__ uint32_t pack2h(__half a, __half b) {
    return (uint32_t)__half_as_ushort(a) |
           ((uint32_t)__half_as_ushort(b) << 16);
}

// ---------------------- prep kernels ---------------------------------------
__global__ void __launch_bounds__(256)
prep_A(const int* __restrict__ e1, const int* __restrict__ r,
       const float* __restrict__ ent_re, const float* __restrict__ ent_im,
       const float* __restrict__ phase) {
    const int b = blockIdx.x;
    const int e = e1[b];
    const int rl = r[b];
    const float* hr = ent_re + (size_t)e * DIM;
    const float* hm = ent_im + (size_t)e * DIM;
    const float* ph = phase + (size_t)rl * DIM;
    for (int d = threadIdx.x; d < DIM; d += 256) {
        float a = hr[d], bb = hm[d], p = ph[d];
        float sn, cs;
        sincosf(p, &sn, &cs);
        float sre = a * cs - bb * sn;
        float sim = a * sn + bb * cs;
        size_t o = (size_t)b * K2 + d;
        g_A[o]       = __float2half_rn(sre);
        g_A[o + DIM] = __float2half_rn(sim);
    }
}

// one block per entity row; 256 threads, each converts 8 floats -> one 16B store
__global__ void __launch_bounds__(256)
prep_B(const float* __restrict__ ent_re, const float* __restrict__ ent_im,
       int row0) {
    const int n = blockIdx.x + row0;
    const int t = threadIdx.x;
    const float* src = (t < 128)
        ? ent_re + (size_t)n * DIM + t * 8
        : ent_im + (size_t)n * DIM + (t - 128) * 8;
    float4 v0 = *(const float4*)src;
    float4 v1 = *(const float4*)(src + 4);
    uint4 o;
    o.x = pack2h(__float2half_rn(v0.x), __float2half_rn(v0.y));
    o.y = pack2h(__float2half_rn(v0.z), __float2half_rn(v0.w));
    o.z = pack2h(__float2half_rn(v1.x), __float2half_rn(v1.y));
    o.w = pack2h(__float2half_rn(v1.z), __float2half_rn(v1.w));
    const size_t doff = (size_t)n * K2 + ((t < 128) ? t * 8 : DIM + (t - 128) * 8);
    *(uint4*)(g_B + doff) = o;
}

// ---------------------- GEMM kernel ----------------------------------------
// 256 threads = 8 warps; warp (wm, wn) owns a 64x32 sub-tile (R5/R11 validated).
__global__ void __launch_bounds__(256, 2)
gemm_kernel(float* __restrict__ out, int tile0) {
    extern __shared__ char smem[];
    const uint32_t sb0 = smem_u32(smem);

    const int tid = threadIdx.x;
    const int lane = tid & 31;
    const int wid = tid >> 5;
    const int wm = wid & 1;        // 2 M-blocks of 64
    const int wn = wid >> 1;       // 4 N-blocks of 32
    const int m0 = blockIdx.x * TILE_M;
    const int n0 = (tile0 + blockIdx.y) * TILE_N;

    const uint32_t aRow = (uint32_t)((wm * 64 + (lane & 15)) * PITCH + (lane >> 4) * 16);
    const uint32_t bRow = (uint32_t)((wn * 32 + (lane & 15)) * PITCH + (lane >> 4) * 16);

    float acc[4][4][4];
#pragma unroll
    for (int a = 0; a < 4; ++a)
#pragma unroll
        for (int b = 0; b < 4; ++b)
#pragma unroll
            for (int c = 0; c < 4; ++c) acc[a][b][c] = 0.f;

    // ---- load one K-chunk (64 halves wide) into stage i%NSTAGE ----
    auto load_chunk = [&](int i) {
        const uint32_t sb = sb0 + (i % NSTAGE) * STG;
        const int kc = i * KC;
#pragma unroll
        for (int j = 0; j < 4; ++j) {
            const int s = tid + j * 256;            // 0..1023
            const int row = s >> 3, c16 = s & 7;
            const uint32_t so = (uint32_t)(row * PITCH + c16 * 16);
            const size_t ga = (size_t)(m0 + row) * K2 + kc + c16 * 8;
            cpasync16(sb + so, g_A + ga);
            const size_t gb = (size_t)(n0 + row) * K2 + kc + c16 * 8; // padded, no clamp
            cpasync16(sb + TSZ + so, g_B + gb);
        }
    };

    load_chunk(0); cp_commit();
    load_chunk(1); cp_commit();

    for (int i = 0; i < NCH; ++i) {
        cp_wait<1>();              // group i complete (stage i%3 ready)
        __syncthreads();           // all warps done with stage (i+2)%3's prior use

        if (i + 2 < NCH) load_chunk(i + 2);
        cp_commit();               // commit (possibly empty) group i+2

        const uint32_t sb = sb0 + (i % NSTAGE) * STG;
#pragma unroll
        for (int kk = 0; kk < 4; ++kk) {
            const uint32_t ko = kk * 32;
            uint32_t ah[4][4], bh[2][4];
#pragma unroll
            for (int mi = 0; mi < 4; ++mi)
                ldsm4(ah[mi], sb + aRow + mi * (16 * PITCH) + ko);
#pragma unroll
            for (int p = 0; p < 2; ++p)
                ldsm4(bh[p], sb + TSZ + bRow + p * (16 * PITCH) + ko);
#pragma unroll
            for (int mi = 0; mi < 4; ++mi)
#pragma unroll
                for (int p = 0; p < 2; ++p) {
                    mma16816(acc[mi][2 * p],     ah[mi], bh[p][0], bh[p][2]);
                    mma16816(acc[mi][2 * p + 1], ah[mi], bh[p][1], bh[p][3]);
                }
        }
    }

    // ---- epilogue (validated mapping) ----
    const int mrow = m0 + wm * 64 + (lane >> 2);
    const int ncol = n0 + wn * 32 + (lane & 3) * 2;
#pragma unroll
    for (int mi = 0; mi < 4; ++mi) {
#pragma unroll
        for (int ni = 0; ni < 4; ++ni) {
            const int col = ncol + ni * 8;
            if (col < N_ENT) {
                const int r0 = mrow + mi * 16;
                float2 v0 = make_float2(acc[mi][ni][0], acc[mi][ni][1]);
                float2 v1 = make_float2(acc[mi][ni][2], acc[mi][ni][3]);
                *(float2*)(out + (size_t)r0 * N_ENT + col) = v0;
                *(float2*)(out + (size_t)(r0 + 8) * N_ENT + col) = v1;
            }
        }
    }
}

// ---------------------------- launch ---------------------------------------
// Graph-parallel schedule (prep_A and prep_B run CONCURRENTLY):
//   legacy:  [fork ev0] prep_A [evA]   gemm_0  gemm_2 ... (even slices)
//   s2:      prep_B_0..15  (evB[s] after each slice)
//   s3:      (waits evA)               gemm_1  gemm_3 ... (odd slices)
// Each gemm slice waits on its own prep_B slice; even slices get the prep_A
// dependency from legacy-stream ordering, odd slices via evA. Join via evJ;
// then everything created here is destroyed.
extern "C" void kernel_launch(void* const* d_in, const int* in_sizes, int n_in,
                              void* d_out, int out_size) {
    const int*   e1     = (const int*)d_in[0];
    const int*   r      = (const int*)d_in[1];
    const float* ent_re = (const float*)d_in[2];
    const float* ent_im = (const float*)d_in[3];
    const float* phase  = (const float*)d_in[4];
    float* out = (float*)d_out;

    cudaFuncSetAttribute(gemm_kernel,
                         cudaFuncAttributeMaxDynamicSharedMemorySize, SMEM_DYN);

    cudaStream_t s2, s3;
    cudaStreamCreateWithFlags(&s2, cudaStreamNonBlocking);
    cudaStreamCreateWithFlags(&s3, cudaStreamNonBlocking);
    cudaEvent_t evFork, evA, evB[SLICES], evJ;
    cudaEventCreateWithFlags(&evFork, cudaEventDisableTiming);
    cudaEventCreateWithFlags(&evA, cudaEventDisableTiming);
    for (int s = 0; s < SLICES; ++s)
        cudaEventCreateWithFlags(&evB[s], cudaEventDisableTiming);
    cudaEventCreateWithFlags(&evJ, cudaEventDisableTiming);

    // fork BEFORE prep_A: prep_B is independent of prep_A
    cudaEventRecord(evFork, 0);
    cudaStreamWaitEvent(s2, evFork, 0);

    prep_A<<<BATCH, 256>>>(e1, r, ent_re, ent_im, phase);   // legacy stream
    cudaEventRecord(evA, 0);
    cudaStreamWaitEvent(s3, evA, 0);    // odd-slice gemms need A ready

    int row0 = 0;
    for (int s = 0; s < SLICES; ++s) {
        int rows = N_ENT - row0 < ROWS_PS ? N_ENT - row0 : ROWS_PS;
        prep_B<<<rows, 256, 0, s2>>>(ent_re, ent_im, row0);
        cudaEventRecord(evB[s], s2);
        row0 += rows;
    }

    int tile0 = 0;
    for (int s = 0; s < SLICES; ++s) {
        const int ntiles = (s < SLICES - 1) ? TPS : (NTILES - TPS * (SLICES - 1));
        cudaStream_t st = (s & 1) ? s3 : 0;
        cudaStreamWaitEvent(st, evB[s], 0);
        dim3 grid(BATCH / TILE_M, ntiles);
        gemm_kernel<<<grid, 256, SMEM_DYN, st>>>(out, tile0);
        tile0 += ntiles;
    }

    // join s3 (and transitively s2) back into the legacy stream
    cudaEventRecord(evJ, s3);
    cudaStreamWaitEvent(0, evJ, 0);

    // ---- teardown: nothing created here may outlive this call ----
    cudaStreamDestroy(s2);
    cudaStreamDestroy(s3);
    cudaEventDestroy(evFork);
    cudaEventDestroy(evA);
    for (int s = 0; s < SLICES; ++s) cudaEventDestroy(evB[s]);
    cudaEventDestroy(evJ);
}